// round 8
// baseline (speedup 1.0000x reference)
#include <cuda_runtime.h>
#include <math.h>
#include <stdint.h>

#define NB   32
#define CC   256
#define C4   64
#define LL   6
#define TT   64
#define VV   25
#define EPS  1e-5f
#define SLOPE 0.2f
#define NPAIR 45

#define CH        8                     // channels per pipeline stage
#define NITER     (CC / CH)             // 32
#define TILE_F    (CH * TT * VV)        // 12800 floats per stage
#define TILE_F4   (TILE_F / 4)          // 3200 float4
#define ROW_F4    400                   // float4 per (t,v) tile of one channel
#define CSTRIDE4  (LL * ROW_F4)         // 2400 float4 between channels
// dyn smem: buf[2][12800] + sh_xt[8][12] + sh_red[4][64]
#define SMEM_FLOATS (2 * TILE_F + 8 * 12 + 4 * 64)
#define SMEM_BYTES  (SMEM_FLOATS * 4)

// scratch (no cudaMalloc allowed)
__device__ float g_s[NB * C4 * LL];           // [n][o][l]
__device__ float g_gate[NB * CC * LL];        // [n][c][l]

// flattened (layer, joint) pairs for the hierarchy means
__constant__ int c_pv[NPAIR] = {
    1,0,20,
    0,20,12,16,2,4,8,
    12,16,2,4,8,13,17,3,5,9,
    13,17,3,5,9,14,18,6,10,
    14,18,6,10,15,19,7,11,
    15,19,7,11,21,22,23,24};
__constant__ int c_off[LL + 1] = {0,3,10,20,29,37,45};
__constant__ float c_inv_cnt[LL] = {1.f/3.f, 1.f/7.f, 1.f/10.f, 1.f/9.f, 1.f/8.f, 1.f/8.f};

__device__ __forceinline__ void cp_async16(void* dst_smem, const void* src) {
    uint32_t d = (uint32_t)__cvta_generic_to_shared(dst_smem);
    asm volatile("cp.async.cg.shared.global [%0], [%1], 16;\n" :: "r"(d), "l"(src));
}
__device__ __forceinline__ void cp_commit() {
    asm volatile("cp.async.commit_group;\n");
}
template <int N>
__device__ __forceinline__ void cp_wait() {
    asm volatile("cp.async.wait_group %0;\n" :: "n"(N));
}

// ---------------------------------------------------------------------------
// Fused kernel: streams x[n,:,l,:,:] once, does T-max + conv_down + BN + ReLU
// + layer-mean all in one pass. One block per (n,l); 256 threads; 2-stage
// cp.async pipeline over channel chunks of 8.
// ---------------------------------------------------------------------------
__global__ __launch_bounds__(256) void k_fused(
    const float* __restrict__ x,
    const float* __restrict__ W_down, const float* __restrict__ b_down,
    const float* __restrict__ g_down, const float* __restrict__ be_down,
    const float* __restrict__ m_down, const float* __restrict__ v_down) {
    extern __shared__ float sm[];
    float4* buf4 = reinterpret_cast<float4*>(sm);          // [2][3200]
    float*  buff = sm;                                     // [2][12800]
    float*  sh_xt = sm + 2 * TILE_F;                       // [8][12]
    float*  sh_red = sh_xt + 8 * 12;                       // [4][64]

    const int b = blockIdx.x;
    const int n = b / LL;
    const int l = b % LL;
    const int p0 = c_off[l];
    const int cnt = c_off[l + 1] - p0;        // 3..10 joints for this layer

    const int t = threadIdx.x;
    const int o = t & 63;
    const int g = t >> 6;
    const int w = t >> 5;                     // warp id 0..7 (= channel in chunk)
    const int lane = t & 31;

    // per-lane joint (hoisted; divergent LDC once)
    const int myv = (lane < cnt) ? c_pv[p0 + lane] : 0;

    const float4* x4 = reinterpret_cast<const float4*>(x);
    // base for (n, c=0, l): ((n*CC + 0)*LL + l) * 400 float4
    const float4* xbase = x4 + ((size_t)n * CC * LL + l) * ROW_F4;
    const float4* W4 = reinterpret_cast<const float4*>(W_down);

    float acc0 = 0.f, acc1 = 0.f, acc2 = 0.f;  // pairs g, g+4, g+8

    // prologue: issue chunk 0 into stage 0
    {
        const float4* src = xbase;             // c0 = 0
        #pragma unroll
        for (int j = 0; j < CH; j++) {
            const float4* sj = src + j * CSTRIDE4;
            cp_async16(&buf4[j * ROW_F4 + t], sj + t);
            if (t < ROW_F4 - 256)
                cp_async16(&buf4[j * ROW_F4 + 256 + t], sj + 256 + t);
        }
        cp_commit();
    }

    for (int it = 0; it < NITER; it++) {
        const int s = it & 1;
        // prefetch W slice for this iteration (L1/L2 resident)
        const float4 w4a = W4[(size_t)o * (CC / 4) + it * 2];
        const float4 w4b = W4[(size_t)o * (CC / 4) + it * 2 + 1];

        // issue next chunk into the other stage
        if (it + 1 < NITER) {
            const float4* src = xbase + (size_t)(it + 1) * CH * CSTRIDE4;
            float4* dst = buf4 + (s ^ 1) * TILE_F4;
            #pragma unroll
            for (int j = 0; j < CH; j++) {
                const float4* sj = src + j * CSTRIDE4;
                cp_async16(&dst[j * ROW_F4 + t], sj + t);
                if (t < ROW_F4 - 256)
                    cp_async16(&dst[j * ROW_F4 + 256 + t], sj + 256 + t);
            }
            cp_commit();
            cp_wait<1>();
        } else {
            cp_wait<0>();
        }
        __syncthreads();

        // T-max: warp w reduces channel j=w, lanes < cnt handle joints
        if (lane < cnt) {
            const float* col = buff + s * TILE_F + w * (TT * VV) + myv;
            float m0 = -INFINITY, m1 = -INFINITY, m2 = -INFINITY, m3 = -INFINITY;
            #pragma unroll
            for (int tt = 0; tt < TT; tt += 4) {
                m0 = fmaxf(m0, col[tt * VV]);
                m1 = fmaxf(m1, col[(tt + 1) * VV]);
                m2 = fmaxf(m2, col[(tt + 2) * VV]);
                m3 = fmaxf(m3, col[(tt + 3) * VV]);
            }
            sh_xt[w * 12 + lane] = fmaxf(fmaxf(m0, m1), fmaxf(m2, m3));
        }
        __syncthreads();

        // GEMM accumulate: thread (o,g) over its <=3 pairs, 8 channels
        float wreg[8] = {w4a.x, w4a.y, w4a.z, w4a.w, w4b.x, w4b.y, w4b.z, w4b.w};
        #pragma unroll
        for (int j = 0; j < CH; j++) {
            const float wj = wreg[j];
            if (g < cnt)     acc0 += wj * sh_xt[j * 12 + g];
            if (g + 4 < cnt) acc1 += wj * sh_xt[j * 12 + g + 4];
            if (g + 8 < cnt) acc2 += wj * sh_xt[j * 12 + g + 8];
        }
    }

    // BN + ReLU per pair, partial mean over this thread's pairs
    const float gs  = g_down[o] * rsqrtf(v_down[o] + EPS);
    const float shb = be_down[o] - m_down[o] * gs;
    const float bd  = b_down[o];
    float ssum = 0.f;
    if (g < cnt)     ssum += fmaxf((acc0 + bd) * gs + shb, 0.f);
    if (g + 4 < cnt) ssum += fmaxf((acc1 + bd) * gs + shb, 0.f);
    if (g + 8 < cnt) ssum += fmaxf((acc2 + bd) * gs + shb, 0.f);
    sh_red[g * 64 + o] = ssum;
    __syncthreads();
    if (t < 64) {
        const float sv = (sh_red[t] + sh_red[64 + t] + sh_red[128 + t] +
                          sh_red[192 + t]) * c_inv_cnt[l];
        g_s[((size_t)n * C4 + t) * LL + l] = sv;
    }
}

// ---------------------------------------------------------------------------
// knn + EdgeConv + aggregate + sigmoid gate. One block per sample.
// ---------------------------------------------------------------------------
__global__ __launch_bounds__(256) void k_mid(
    const float* __restrict__ W_edge, const float* __restrict__ g_edge,
    const float* __restrict__ be_edge, const float* __restrict__ m_edge,
    const float* __restrict__ v_edge, const float* __restrict__ W_agg,
    const float* __restrict__ b_agg) {
    const int n = blockIdx.x;
    const int t = threadIdx.x;

    __shared__ float sh_s[C4][LL];
    __shared__ float sh_G[LL * LL];
    __shared__ int   sh_idx[LL][3];
    __shared__ float sh_e[C4][LL];

    for (int i = t; i < C4 * LL; i += 256)
        sh_s[i / LL][i % LL] = g_s[(size_t)n * C4 * LL + i];
    __syncthreads();

    // Gram matrix
    if (t < LL * LL) {
        const int i = t / LL, j = t % LL;
        float acc = 0.f;
        #pragma unroll 8
        for (int o = 0; o < C4; o++) acc += sh_s[o][i] * sh_s[o][j];
        sh_G[t] = acc;
    }
    __syncthreads();

    // top-3 neighbors by -||si-sj||^2 (stable tie-break matching lax.top_k)
    if (t < LL) {
        float d[LL];
        bool used[LL];
        const float sqi = sh_G[t * LL + t];
        #pragma unroll
        for (int j = 0; j < LL; j++) {
            d[j] = 2.f * sh_G[t * LL + j] - sqi - sh_G[j * LL + j];
            used[j] = false;
        }
        #pragma unroll
        for (int k = 0; k < 3; k++) {
            float best = -INFINITY; int bi = 0;
            #pragma unroll
            for (int j = 0; j < LL; j++)
                if (!used[j] && d[j] > best) { best = d[j]; bi = j; }
            used[bi] = true;
            sh_idx[t][k] = bi;
        }
    }
    __syncthreads();

    // EdgeConv + BN + leaky + max over k -> e[o][l]
    for (int item = t; item < LL * C4; item += 256) {
        const int o = item & 63;
        const int l = item >> 6;
        const float* w1 = W_edge + o * (2 * C4);
        const float* w2 = w1 + C4;
        const int n0 = sh_idx[l][0], n1 = sh_idx[l][1], n2 = sh_idx[l][2];
        float base = 0.f, a0 = 0.f, a1 = 0.f, a2 = 0.f;
        #pragma unroll 4
        for (int c = 0; c < C4; c++) {
            const float w = w1[c];
            base += (w2[c] - w) * sh_s[c][l];
            a0 += w * sh_s[c][n0];
            a1 += w * sh_s[c][n1];
            a2 += w * sh_s[c][n2];
        }
        const float gs  = g_edge[o] * rsqrtf(v_edge[o] + EPS);
        const float shb = be_edge[o] - m_edge[o] * gs;
        float m = -INFINITY;
        float ys[3] = {a0 + base, a1 + base, a2 + base};
        #pragma unroll
        for (int k = 0; k < 3; k++) {
            float y = ys[k] * gs + shb;
            y = fmaxf(y, 0.f) + SLOPE * fminf(y, 0.f);
            m = fmaxf(m, y);
        }
        sh_e[o][l] = m;
    }
    __syncthreads();

    // att = W_agg @ e + b_agg ; gate = sigmoid
    {
        const int oc = t;                      // 256 threads == C outputs
        float a[LL];
        const float bb = b_agg[oc];
        #pragma unroll
        for (int l = 0; l < LL; l++) a[l] = bb;
        const float* wr = W_agg + oc * C4;
        #pragma unroll 4
        for (int c = 0; c < C4; c++) {
            const float w = wr[c];
            #pragma unroll
            for (int l = 0; l < LL; l++) a[l] += w * sh_e[c][l];
        }
        float* gp = g_gate + ((size_t)n * CC + oc) * LL;
        #pragma unroll
        for (int l = 0; l < LL; l++)
            gp[l] = 1.f / (1.f + expf(-a[l]));
    }
}

// ---------------------------------------------------------------------------
// out[n,c,t,v] = sum_l x[n,c,l,t,v] * gate[n,c,l]   (float4)
// ---------------------------------------------------------------------------
__global__ __launch_bounds__(256) void k_gatesum(const float* __restrict__ x,
                                                 float* __restrict__ out) {
    const int gid = blockIdx.x * 256 + threadIdx.x;     // [0, 32*256*400)
    const int tv4 = gid % 400;
    const int nc  = gid / 400;
    const float4* xb = reinterpret_cast<const float4*>(x) + (size_t)nc * (LL * 400) + tv4;
    const float* gp = g_gate + (size_t)nc * LL;
    float4 acc = make_float4(0.f, 0.f, 0.f, 0.f);
    #pragma unroll
    for (int l = 0; l < LL; l++) {
        const float g = gp[l];
        const float4 xv = xb[l * 400];
        acc.x += xv.x * g; acc.y += xv.y * g;
        acc.z += xv.z * g; acc.w += xv.w * g;
    }
    reinterpret_cast<float4*>(out)[(size_t)nc * 400 + tv4] = acc;
}

// ---------------------------------------------------------------------------
extern "C" void kernel_launch(void* const* d_in, const int* in_sizes, int n_in,
                              void* d_out, int out_size) {
    const float* x       = (const float*)d_in[0];
    const float* W_down  = (const float*)d_in[1];
    const float* b_down  = (const float*)d_in[2];
    const float* g_down  = (const float*)d_in[3];
    const float* be_down = (const float*)d_in[4];
    const float* m_down  = (const float*)d_in[5];
    const float* v_down  = (const float*)d_in[6];
    const float* W_edge  = (const float*)d_in[7];
    const float* g_edge  = (const float*)d_in[8];
    const float* be_edge = (const float*)d_in[9];
    const float* m_edge  = (const float*)d_in[10];
    const float* v_edge  = (const float*)d_in[11];
    const float* W_agg   = (const float*)d_in[12];
    const float* b_agg   = (const float*)d_in[13];
    float* out = (float*)d_out;

    (void)cudaFuncSetAttribute(k_fused,
                               cudaFuncAttributeMaxDynamicSharedMemorySize,
                               SMEM_BYTES);
    k_fused<<<NB * LL, 256, SMEM_BYTES>>>(x, W_down, b_down, g_down, be_down,
                                          m_down, v_down);
    k_mid<<<NB, 256>>>(W_edge, g_edge, be_edge, m_edge, v_edge, W_agg, b_agg);
    k_gatesum<<<(NB * CC * 400) / 256, 256>>>(x, out);
}

// round 9
// speedup vs baseline: 1.3363x; 1.3363x over previous
#include <cuda_runtime.h>
#include <math.h>

#define NB   32
#define CC   256
#define C4   64
#define LL   6
#define TT   64
#define VV   25
#define EPS  1e-5f
#define SLOPE 0.2f
#define NPAIR 45

// scratch (no cudaMalloc allowed)
__device__ float g_xt[NB * CC * LL * VV];     // [n][c][l][v]
__device__ float g_s[NB * C4 * LL];           // [n][o][l]
__device__ float g_gate[NB * CC * LL];        // [n][c][l]

// flattened (layer, joint) pairs for the hierarchy means
__constant__ int c_pv[NPAIR] = {
    1,0,20,
    0,20,12,16,2,4,8,
    12,16,2,4,8,13,17,3,5,9,
    13,17,3,5,9,14,18,6,10,
    14,18,6,10,15,19,7,11,
    15,19,7,11,21,22,23,24};
__constant__ int c_off[LL + 1] = {0,3,10,20,29,37,45};
__constant__ float c_inv_cnt[LL] = {1.f/3.f, 1.f/7.f, 1.f/10.f, 1.f/9.f, 1.f/8.f, 1.f/8.f};

// ---------------------------------------------------------------------------
// Kernel 1 (R3-proven, 49.9us @ 81.5% DRAM): x_t[n,c,l,v] = max_t x[n,c,l,t,v]
// one block per (n,c,l); 1600 floats loaded as 400 float4 into smem.
// ---------------------------------------------------------------------------
__global__ __launch_bounds__(128) void k_tmax(const float* __restrict__ x) {
    __shared__ float4 tile4[400];
    float* tile = reinterpret_cast<float*>(tile4);
    const int b = blockIdx.x;                 // (n*C + c)*L + l
    const float4* xb = reinterpret_cast<const float4*>(x) + (size_t)b * 400;
    const int tid = threadIdx.x;
    #pragma unroll
    for (int i = 0; i < 3; i++) tile4[tid + i * 128] = xb[tid + i * 128];
    if (tid < 16) tile4[tid + 384] = xb[tid + 384];
    __syncthreads();
    if (tid < VV) {
        float m = tile[tid];
        #pragma unroll
        for (int t = 1; t < TT; t++) m = fmaxf(m, tile[t * VV + tid]);
        g_xt[(size_t)b * VV + tid] = m;
    }
}

// ---------------------------------------------------------------------------
// Kernel 2: s[n][o][l] = mean_v relu(bn(W_down @ x_t + b)) for layer l's joints
// grid = NB*LL; 256 threads = (o = t&63) x (g = t>>6 : c-quarter).
// W segment lives in registers; X rows in smem, read as float4 broadcasts.
// ---------------------------------------------------------------------------
__global__ __launch_bounds__(256) void k_s(
    const float* __restrict__ W_down, const float* __restrict__ b_down,
    const float* __restrict__ g_down, const float* __restrict__ be_down,
    const float* __restrict__ m_down, const float* __restrict__ v_down) {
    const int n = blockIdx.x / LL;
    const int l = blockIdx.x % LL;
    const int p0 = c_off[l];
    const int cnt = c_off[l + 1] - p0;        // 3..10 joints in this layer

    __shared__ float shX[10 * 256];           // X rows; reused as partials

    const int t = threadIdx.x;
    const int o = t & 63;
    const int g = t >> 6;

    // gather X: row p = joint, 256 channels (stride L*V floats in g_xt)
    const float* xb = g_xt + ((size_t)n * CC * LL + l) * VV;
    for (int i = t; i < cnt * 256; i += 256) {
        const int p = i >> 8, c = i & 255;
        shX[p * 256 + c] = xb[(size_t)c * (LL * VV) + c_pv[p0 + p]];
    }

    // W segment -> registers (L2-resident after first wave)
    float wreg[64];
    {
        const float4* wr = reinterpret_cast<const float4*>(W_down + o * CC + g * 64);
        #pragma unroll
        for (int i = 0; i < 16; i++) {
            const float4 w = wr[i];
            wreg[4*i] = w.x; wreg[4*i+1] = w.y; wreg[4*i+2] = w.z; wreg[4*i+3] = w.w;
        }
    }
    __syncthreads();

    float acc[10];
    #pragma unroll
    for (int p = 0; p < 10; p++) acc[p] = 0.f;
    #pragma unroll
    for (int p = 0; p < 10; p++) {
        if (p < cnt) {
            const float4* xp = reinterpret_cast<const float4*>(shX + p * 256 + g * 64);
            float a = 0.f;
            #pragma unroll
            for (int i = 0; i < 16; i++) {
                const float4 xv = xp[i];
                a += wreg[4*i] * xv.x + wreg[4*i+1] * xv.y
                   + wreg[4*i+2] * xv.z + wreg[4*i+3] * xv.w;
            }
            acc[p] = a;
        }
    }
    __syncthreads();                          // all X reads done -> reuse shX
    float* parts = shX;                       // [g][p][o]
    #pragma unroll
    for (int p = 0; p < 10; p++)
        if (p < cnt) parts[(g * 10 + p) * 64 + o] = acc[p];
    __syncthreads();

    if (t < 64) {
        const float gs  = g_down[t] * rsqrtf(v_down[t] + EPS);
        const float shb = be_down[t] - m_down[t] * gs;
        const float bd  = b_down[t];
        float ssum = 0.f;
        #pragma unroll
        for (int p = 0; p < 10; p++) {
            if (p < cnt) {
                const float y = (parts[p * 64 + t] + parts[(10 + p) * 64 + t] +
                                 parts[(20 + p) * 64 + t] + parts[(30 + p) * 64 + t]
                                 + bd) * gs + shb;
                ssum += fmaxf(y, 0.f);
            }
        }
        g_s[((size_t)n * C4 + t) * LL + l] = ssum * c_inv_cnt[l];
    }
}

// ---------------------------------------------------------------------------
// Kernel 3: knn + EdgeConv + aggregate + sigmoid gate. One block per sample.
// ---------------------------------------------------------------------------
__global__ __launch_bounds__(256) void k_mid(
    const float* __restrict__ W_edge, const float* __restrict__ g_edge,
    const float* __restrict__ be_edge, const float* __restrict__ m_edge,
    const float* __restrict__ v_edge, const float* __restrict__ W_agg,
    const float* __restrict__ b_agg) {
    const int n = blockIdx.x;
    const int t = threadIdx.x;

    __shared__ float sh_s[C4][LL];
    __shared__ float sh_G[LL * LL];
    __shared__ int   sh_idx[LL][3];
    __shared__ float sh_e[C4][LL];

    for (int i = t; i < C4 * LL; i += 256)
        sh_s[i / LL][i % LL] = g_s[(size_t)n * C4 * LL + i];
    __syncthreads();

    // Gram matrix
    if (t < LL * LL) {
        const int i = t / LL, j = t % LL;
        float acc = 0.f;
        #pragma unroll 8
        for (int o = 0; o < C4; o++) acc += sh_s[o][i] * sh_s[o][j];
        sh_G[t] = acc;
    }
    __syncthreads();

    // top-3 neighbors by -||si-sj||^2 (stable tie-break matching lax.top_k)
    if (t < LL) {
        float d[LL];
        bool used[LL];
        const float sqi = sh_G[t * LL + t];
        #pragma unroll
        for (int j = 0; j < LL; j++) {
            d[j] = 2.f * sh_G[t * LL + j] - sqi - sh_G[j * LL + j];
            used[j] = false;
        }
        #pragma unroll
        for (int k = 0; k < 3; k++) {
            float best = -INFINITY; int bi = 0;
            #pragma unroll
            for (int j = 0; j < LL; j++)
                if (!used[j] && d[j] > best) { best = d[j]; bi = j; }
            used[bi] = true;
            sh_idx[t][k] = bi;
        }
    }
    __syncthreads();

    // EdgeConv + BN + leaky + max over k -> e[o][l]
    for (int item = t; item < LL * C4; item += 256) {
        const int o = item & 63;
        const int l = item >> 6;
        const float* w1 = W_edge + o * (2 * C4);
        const float* w2 = w1 + C4;
        const int n0 = sh_idx[l][0], n1 = sh_idx[l][1], n2 = sh_idx[l][2];
        float base = 0.f, a0 = 0.f, a1 = 0.f, a2 = 0.f;
        #pragma unroll 4
        for (int c = 0; c < C4; c++) {
            const float w = w1[c];
            base += (w2[c] - w) * sh_s[c][l];
            a0 += w * sh_s[c][n0];
            a1 += w * sh_s[c][n1];
            a2 += w * sh_s[c][n2];
        }
        const float gs  = g_edge[o] * rsqrtf(v_edge[o] + EPS);
        const float shb = be_edge[o] - m_edge[o] * gs;
        float m = -INFINITY;
        float ys[3] = {a0 + base, a1 + base, a2 + base};
        #pragma unroll
        for (int k = 0; k < 3; k++) {
            float y = ys[k] * gs + shb;
            y = fmaxf(y, 0.f) + SLOPE * fminf(y, 0.f);
            m = fmaxf(m, y);
        }
        sh_e[o][l] = m;
    }
    __syncthreads();

    // att = W_agg @ e + b_agg ; gate = sigmoid
    {
        const int oc = t;                      // 256 threads == C outputs
        float a[LL];
        const float bb = b_agg[oc];
        #pragma unroll
        for (int l = 0; l < LL; l++) a[l] = bb;
        const float* wr = W_agg + oc * C4;
        #pragma unroll 4
        for (int c = 0; c < C4; c++) {
            const float w = wr[c];
            #pragma unroll
            for (int l = 0; l < LL; l++) a[l] += w * sh_e[c][l];
        }
        float* gp = g_gate + ((size_t)n * CC + oc) * LL;
        #pragma unroll
        for (int l = 0; l < LL; l++)
            gp[l] = 1.f / (1.f + expf(-a[l]));
    }
}

// ---------------------------------------------------------------------------
// Kernel 4: out[n,c,t,v] = sum_l x[n,c,l,t,v] * gate[n,c,l]   (float4)
// ---------------------------------------------------------------------------
__global__ __launch_bounds__(256) void k_gatesum(const float* __restrict__ x,
                                                 float* __restrict__ out) {
    const int gid = blockIdx.x * 256 + threadIdx.x;     // [0, 32*256*400)
    const int tv4 = gid % 400;
    const int nc  = gid / 400;
    const float4* xb = reinterpret_cast<const float4*>(x) + (size_t)nc * (LL * 400) + tv4;
    const float* gp = g_gate + (size_t)nc * LL;
    float4 acc = make_float4(0.f, 0.f, 0.f, 0.f);
    #pragma unroll
    for (int l = 0; l < LL; l++) {
        const float g = gp[l];
        const float4 xv = xb[l * 400];
        acc.x += xv.x * g; acc.y += xv.y * g;
        acc.z += xv.z * g; acc.w += xv.w * g;
    }
    reinterpret_cast<float4*>(out)[(size_t)nc * 400 + tv4] = acc;
}

// ---------------------------------------------------------------------------
extern "C" void kernel_launch(void* const* d_in, const int* in_sizes, int n_in,
                              void* d_out, int out_size) {
    const float* x       = (const float*)d_in[0];
    const float* W_down  = (const float*)d_in[1];
    const float* b_down  = (const float*)d_in[2];
    const float* g_down  = (const float*)d_in[3];
    const float* be_down = (const float*)d_in[4];
    const float* m_down  = (const float*)d_in[5];
    const float* v_down  = (const float*)d_in[6];
    const float* W_edge  = (const float*)d_in[7];
    const float* g_edge  = (const float*)d_in[8];
    const float* be_edge = (const float*)d_in[9];
    const float* m_edge  = (const float*)d_in[10];
    const float* v_edge  = (const float*)d_in[11];
    const float* W_agg   = (const float*)d_in[12];
    const float* b_agg   = (const float*)d_in[13];
    float* out = (float*)d_out;

    k_tmax<<<NB * CC * LL, 128>>>(x);
    k_s<<<NB * LL, 256>>>(W_down, b_down, g_down, be_down, m_down, v_down);
    k_mid<<<NB, 256>>>(W_edge, g_edge, be_edge, m_edge, v_edge, W_agg, b_agg);
    k_gatesum<<<(NB * CC * 400) / 256, 256>>>(x, out);
}

// round 10
// speedup vs baseline: 1.4713x; 1.1011x over previous
#include <cuda_runtime.h>
#include <math.h>

#define NB   32
#define CC   256
#define C4   64
#define LL   6
#define TT   64
#define VV   25
#define EPS  1e-5f
#define SLOPE 0.2f
#define NPAIR 45

// scratch (no cudaMalloc allowed)
__device__ float g_xt[NB * CC * LL * VV];     // [n][c][l][v]
__device__ float g_gate[NB * CC * LL];        // [n][c][l]

// flattened (layer, joint) pairs for the hierarchy means
__constant__ int c_pv[NPAIR] = {
    1,0,20,
    0,20,12,16,2,4,8,
    12,16,2,4,8,13,17,3,5,9,
    13,17,3,5,9,14,18,6,10,
    14,18,6,10,15,19,7,11,
    15,19,7,11,21,22,23,24};
__constant__ int c_off[LL + 1] = {0,3,10,20,29,37,45};
__constant__ float c_inv_cnt[LL] = {1.f/3.f, 1.f/7.f, 1.f/10.f, 1.f/9.f, 1.f/8.f, 1.f/8.f};

// ---------------------------------------------------------------------------
// Kernel 1 (R3-proven, 49.9us @ 81.5% DRAM): x_t[n,c,l,v] = max_t x[n,c,l,t,v]
// ---------------------------------------------------------------------------
__global__ __launch_bounds__(128) void k_tmax(const float* __restrict__ x) {
    __shared__ float4 tile4[400];
    float* tile = reinterpret_cast<float*>(tile4);
    const int b = blockIdx.x;                 // (n*C + c)*L + l
    const float4* xb = reinterpret_cast<const float4*>(x) + (size_t)b * 400;
    const int tid = threadIdx.x;
    #pragma unroll
    for (int i = 0; i < 3; i++) tile4[tid + i * 128] = xb[tid + i * 128];
    if (tid < 16) tile4[tid + 384] = xb[tid + 384];
    __syncthreads();
    if (tid < VV) {
        float m = tile[tid];
        #pragma unroll
        for (int t = 1; t < TT; t++) m = fmaxf(m, tile[t * VV + tid]);
        g_xt[(size_t)b * VV + tid] = m;
    }
}

// ---------------------------------------------------------------------------
// Kernel 2: whole middle per sample. One block per n, 256 threads.
// Stage 1: per-layer down-projection + BN + ReLU + joint-mean -> sh_s (smem).
// Stage 2: Gram / top-3 / EdgeConv (W_edge in padded smem) / agg / sigmoid.
// ---------------------------------------------------------------------------
__global__ __launch_bounds__(256) void k_smid(
    const float* __restrict__ W_down, const float* __restrict__ b_down,
    const float* __restrict__ g_down, const float* __restrict__ be_down,
    const float* __restrict__ m_down, const float* __restrict__ v_down,
    const float* __restrict__ W_edge, const float* __restrict__ g_edge,
    const float* __restrict__ be_edge, const float* __restrict__ m_edge,
    const float* __restrict__ v_edge, const float* __restrict__ W_agg,
    const float* __restrict__ b_agg) {
    const int n = blockIdx.x;
    const int t = threadIdx.x;
    const int o = t & 63;
    const int g = t >> 6;

    __shared__ float shX[10 * 256];           // gathered X rows; reused as parts
    __shared__ float shWe[64 * 129];          // W_edge, padded (conflict-free)
    __shared__ float sh_s[C4][LL];
    __shared__ float sh_G[LL * LL];
    __shared__ int   sh_idx[LL][3];
    __shared__ float sh_e[C4][LL];

    // stage W_edge into smem (coalesced float4, stride pad 129)
    for (int i = t; i < 64 * 32; i += 256) {
        const int r = i >> 5, c4 = i & 31;
        const float4 w = reinterpret_cast<const float4*>(W_edge + r * 128)[c4];
        float* d = &shWe[r * 129 + c4 * 4];
        d[0] = w.x; d[1] = w.y; d[2] = w.z; d[3] = w.w;
    }

    // W_down segment -> registers (row o, quarter g)
    float wreg[64];
    {
        const float4* wr = reinterpret_cast<const float4*>(W_down + o * CC + g * 64);
        #pragma unroll
        for (int i = 0; i < 16; i++) {
            const float4 w = wr[i];
            wreg[4*i] = w.x; wreg[4*i+1] = w.y; wreg[4*i+2] = w.z; wreg[4*i+3] = w.w;
        }
    }

    // ---- Stage 1: s for all 6 layers ----
    for (int l = 0; l < LL; l++) {
        const int p0 = c_off[l];
        const int cnt = c_off[l + 1] - p0;
        const float* xb = g_xt + ((size_t)n * CC * LL + l) * VV;
        __syncthreads();                      // shX free from previous iter
        for (int i = t; i < cnt * 256; i += 256) {
            const int p = i >> 8, c = i & 255;   // p uniform per iter, c = t
            shX[p * 256 + c] = xb[(size_t)c * (LL * VV) + c_pv[p0 + p]];
        }
        __syncthreads();

        float acc[10];
        #pragma unroll
        for (int p = 0; p < 10; p++) acc[p] = 0.f;
        #pragma unroll
        for (int p = 0; p < 10; p++) {
            if (p < cnt) {
                const float4* xp = reinterpret_cast<const float4*>(shX + p * 256 + g * 64);
                float a = 0.f;
                #pragma unroll
                for (int i = 0; i < 16; i++) {
                    const float4 xv = xp[i];
                    a += wreg[4*i] * xv.x + wreg[4*i+1] * xv.y
                       + wreg[4*i+2] * xv.z + wreg[4*i+3] * xv.w;
                }
                acc[p] = a;
            }
        }
        __syncthreads();                      // X reads done -> reuse shX
        float* parts = shX;                   // [g][p][o]
        #pragma unroll
        for (int p = 0; p < 10; p++)
            if (p < cnt) parts[(g * 10 + p) * 64 + o] = acc[p];
        __syncthreads();

        if (t < 64) {
            const float gs  = g_down[t] * rsqrtf(v_down[t] + EPS);
            const float shb = be_down[t] - m_down[t] * gs;
            const float bd  = b_down[t];
            float ssum = 0.f;
            #pragma unroll
            for (int p = 0; p < 10; p++) {
                if (p < cnt) {
                    const float y = (parts[p * 64 + t] + parts[(10 + p) * 64 + t] +
                                     parts[(20 + p) * 64 + t] + parts[(30 + p) * 64 + t]
                                     + bd) * gs + shb;
                    ssum += fmaxf(y, 0.f);
                }
            }
            sh_s[t][l] = ssum * c_inv_cnt[l];
        }
    }
    __syncthreads();

    // ---- Stage 2a: Gram matrix ----
    if (t < LL * LL) {
        const int i = t / LL, j = t % LL;
        float acc = 0.f;
        #pragma unroll 8
        for (int c = 0; c < C4; c++) acc += sh_s[c][i] * sh_s[c][j];
        sh_G[t] = acc;
    }
    __syncthreads();

    // ---- Stage 2b: top-3 neighbors (stable tie-break matching lax.top_k) ----
    if (t < LL) {
        float d[LL];
        bool used[LL];
        const float sqi = sh_G[t * LL + t];
        #pragma unroll
        for (int j = 0; j < LL; j++) {
            d[j] = 2.f * sh_G[t * LL + j] - sqi - sh_G[j * LL + j];
            used[j] = false;
        }
        #pragma unroll
        for (int k = 0; k < 3; k++) {
            float best = -INFINITY; int bi = 0;
            #pragma unroll
            for (int j = 0; j < LL; j++)
                if (!used[j] && d[j] > best) { best = d[j]; bi = j; }
            used[bi] = true;
            sh_idx[t][k] = bi;
        }
    }
    __syncthreads();

    // ---- Stage 2c: EdgeConv + BN + leaky + max over k -> sh_e ----
    for (int item = t; item < LL * C4; item += 256) {
        const int oo = item & 63;
        const int l  = item >> 6;
        const float* w1 = &shWe[oo * 129];
        const float* w2 = w1 + 64;
        const int n0 = sh_idx[l][0], n1 = sh_idx[l][1], n2 = sh_idx[l][2];
        float base = 0.f, a0 = 0.f, a1 = 0.f, a2 = 0.f;
        #pragma unroll 8
        for (int c = 0; c < C4; c++) {
            const float w = w1[c];
            base += (w2[c] - w) * sh_s[c][l];
            a0 += w * sh_s[c][n0];
            a1 += w * sh_s[c][n1];
            a2 += w * sh_s[c][n2];
        }
        const float gs  = g_edge[oo] * rsqrtf(v_edge[oo] + EPS);
        const float shb = be_edge[oo] - m_edge[oo] * gs;
        float m = -INFINITY;
        float ys[3] = {a0 + base, a1 + base, a2 + base};
        #pragma unroll
        for (int k = 0; k < 3; k++) {
            float y = ys[k] * gs + shb;
            y = fmaxf(y, 0.f) + SLOPE * fminf(y, 0.f);
            m = fmaxf(m, y);
        }
        sh_e[oo][l] = m;
    }
    __syncthreads();

    // ---- Stage 2d: att = W_agg @ e + b_agg ; gate = sigmoid ----
    {
        const int oc = t;                      // 256 threads == C outputs
        float a[LL];
        const float bb = b_agg[oc];
        #pragma unroll
        for (int l = 0; l < LL; l++) a[l] = bb;
        const float4* wr = reinterpret_cast<const float4*>(W_agg + oc * C4);
        #pragma unroll
        for (int i = 0; i < 16; i++) {
            const float4 w = wr[i];
            const int c = 4 * i;
            #pragma unroll
            for (int l = 0; l < LL; l++)
                a[l] += w.x * sh_e[c][l] + w.y * sh_e[c+1][l]
                      + w.z * sh_e[c+2][l] + w.w * sh_e[c+3][l];
        }
        float* gp = g_gate + ((size_t)n * CC + oc) * LL;
        #pragma unroll
        for (int l = 0; l < LL; l++)
            gp[l] = 1.f / (1.f + expf(-a[l]));
    }
}

// ---------------------------------------------------------------------------
// Kernel 3: out[n,c,t,v] = sum_l x[n,c,l,t,v] * gate[n,c,l]   (float4)
// ---------------------------------------------------------------------------
__global__ __launch_bounds__(256) void k_gatesum(const float* __restrict__ x,
                                                 float* __restrict__ out) {
    const int gid = blockIdx.x * 256 + threadIdx.x;     // [0, 32*256*400)
    const int tv4 = gid % 400;
    const int nc  = gid / 400;
    const float4* xb = reinterpret_cast<const float4*>(x) + (size_t)nc * (LL * 400) + tv4;
    const float* gp = g_gate + (size_t)nc * LL;
    float4 acc = make_float4(0.f, 0.f, 0.f, 0.f);
    #pragma unroll
    for (int l = 0; l < LL; l++) {
        const float g = gp[l];
        const float4 xv = xb[l * 400];
        acc.x += xv.x * g; acc.y += xv.y * g;
        acc.z += xv.z * g; acc.w += xv.w * g;
    }
    reinterpret_cast<float4*>(out)[(size_t)nc * 400 + tv4] = acc;
}

// ---------------------------------------------------------------------------
extern "C" void kernel_launch(void* const* d_in, const int* in_sizes, int n_in,
                              void* d_out, int out_size) {
    const float* x       = (const float*)d_in[0];
    const float* W_down  = (const float*)d_in[1];
    const float* b_down  = (const float*)d_in[2];
    const float* g_down  = (const float*)d_in[3];
    const float* be_down = (const float*)d_in[4];
    const float* m_down  = (const float*)d_in[5];
    const float* v_down  = (const float*)d_in[6];
    const float* W_edge  = (const float*)d_in[7];
    const float* g_edge  = (const float*)d_in[8];
    const float* be_edge = (const float*)d_in[9];
    const float* m_edge  = (const float*)d_in[10];
    const float* v_edge  = (const float*)d_in[11];
    const float* W_agg   = (const float*)d_in[12];
    const float* b_agg   = (const float*)d_in[13];
    float* out = (float*)d_out;

    k_tmax<<<NB * CC * LL, 128>>>(x);
    k_smid<<<NB, 256>>>(W_down, b_down, g_down, be_down, m_down, v_down,
                        W_edge, g_edge, be_edge, m_edge, v_edge, W_agg, b_agg);
    k_gatesum<<<(NB * CC * 400) / 256, 256>>>(x, out);
}